// round 10
// baseline (speedup 1.0000x reference)
#include <cuda_runtime.h>
#include <cuda_fp16.h>

#define D      4096
#define R      16
#define NS     192
#define LB     1280
#define TPB    256
#define CH     8
#define SLOTS  5                      // chunk slots per adapter (m <= 40)
#define NCH    (NS * SLOTS)           // 960
#define PARTS  4
#define IPT    (LB / TPB)             // 5

typedef unsigned long long ull;
union U8 { uint4 u; __half2 h2[4]; __half h[8]; };

// ---- device scratch ----
__device__ ull   g_hp[NCH * PARTS * 64];        // fp32x2 h partials
__device__ ull   g_h[NCH * 64];                 // fp16x2 quantized (2h), layout r*4+jp
__device__ uint4 g_y4[(size_t)1024 * (D / 8)];  // fp16 y, summed-segment rows only

// ---- packed f32x2 helpers (sm_100+) ----
__device__ __forceinline__ ull pk2(float lo, float hi) {
    ull r; asm("mov.b64 %0, {%1, %2};" : "=l"(r) : "f"(lo), "f"(hi)); return r;
}
__device__ __forceinline__ void up2(ull v, float& lo, float& hi) {
    asm("mov.b64 {%0, %1}, %2;" : "=f"(lo), "=f"(hi) : "l"(v));
}
__device__ __forceinline__ ull ffma2(ull a, ull b, ull c) {
    ull d; asm("fma.rn.f32x2 %0, %1, %2, %3;" : "=l"(d) : "l"(a), "l"(b), "l"(c)); return d;
}
__device__ __forceinline__ ull fadd2(ull a, ull b) {
    ull d; asm("add.rn.f32x2 %0, %1, %2;" : "=l"(d) : "l"(a), "l"(b)); return d;
}

// in-block gather scan: returns m; fills slist (ascending row ids) for adapter w.
// All 256 threads must participate. Caller syncs AFTER a live-check return-gate.
struct ScanSm { int swarp[8]; int stot; int slist[64]; };

__device__ __forceinline__ int scan_rows(const int* __restrict__ wids, int w,
                                         ScanSm* S, int t, int lane, int W,
                                         int* excl_out, int* mt) {
    int base = t * IPT;
    int cnt = 0;
#pragma unroll
    for (int k = 0; k < IPT; k++) {
        mt[k] = (wids[base + k] == w) ? 1 : 0;
        cnt += mt[k];
    }
    int incl = cnt;
#pragma unroll
    for (int o = 1; o < 32; o <<= 1) {
        int v = __shfl_up_sync(0xffffffffu, incl, o);
        if (lane >= o) incl += v;
    }
    if (lane == 31) S->swarp[W] = incl;
    __syncthreads();
    if (t == 0) {
        int s = 0;
#pragma unroll
        for (int q = 0; q < 8; q++) { int v = S->swarp[q]; S->swarp[q] = s; s += v; }
        S->stot = s;
    }
    __syncthreads();
    *excl_out = incl - cnt + S->swarp[W];
    return S->stot;
}

// ---------------------------------------------------------------- k_h1: partial h
__global__ void __launch_bounds__(TPB) k_h1(
    const float* __restrict__ x,
    const float* __restrict__ lA,
    const int*   __restrict__ xids,
    const int*   __restrict__ wids)
{
    int chunk = blockIdx.x >> 2;
    int part  = blockIdx.x & 3;
    int w     = chunk / SLOTS;
    int slot  = chunk % SLOTS;

    __shared__ uint4 xh[1024];          // 16 KB: d-quarter, 8 rows fp16 packed
    __shared__ ull   red[8 * 4 * 16];   // 4 KB
    __shared__ ScanSm S;
    __shared__ int   shxid[8];

    int t = threadIdx.x, lane = t & 31, W = t >> 5;
    int mt[IPT], excl;
    int m = scan_rows(wids, w, &S, t, lane, W, &excl, mt);
    if (slot * CH >= m) return;         // dead slot
    int base = t * IPT;
#pragma unroll
    for (int k = 0; k < IPT; k++)
        if (mt[k]) S.slist[excl++] = base + k;
    __syncthreads();

    int nr = min(CH, m - slot * CH);
    if (t < CH) {
        int rr = (t < nr) ? S.slist[slot * CH + t] : -1;
        shxid[t] = (rr >= 0) ? xids[rr] : -1;
    }
    __syncthreads();

    // stage x quarter (lossless fp16: inputs are fp16 upcast to f32)
    int dg0 = part * 1024;
    {
        int xid[8];
#pragma unroll
        for (int j = 0; j < 8; j++) xid[j] = shxid[j];
#pragma unroll
        for (int i = 0; i < 4; i++) {
            int dl = t + i * TPB;
            int dg = dg0 + dl;
            float v[8];
#pragma unroll
            for (int j = 0; j < 8; j++)
                v[j] = (xid[j] >= 0) ? x[(size_t)xid[j] * D + dg] : 0.0f;
            __half2 p0 = __floats2half2_rn(v[0], v[1]);
            __half2 p1 = __floats2half2_rn(v[2], v[3]);
            __half2 p2 = __floats2half2_rn(v[4], v[5]);
            __half2 p3 = __floats2half2_rn(v[6], v[7]);
            xh[dl] = make_uint4(*(unsigned*)&p0, *(unsigned*)&p1,
                                *(unsigned*)&p2, *(unsigned*)&p3);
        }
    }
    __syncthreads();

    // phase 1 over 128-d warp stripe
    const float* A = lA + (size_t)w * D * R;
    ull accp[4][4];
#pragma unroll
    for (int jp = 0; jp < 4; jp++)
#pragma unroll
        for (int k = 0; k < 4; k++) accp[jp][k] = 0ull;

    int dwl = W * 128;
#pragma unroll 4
    for (int s = 0; s < 16; s++) {
        float4 a4 = ((const float4*)A)[(dg0 + dwl + s * 8) * 4 + lane];
        ull av0 = pk2(a4.x, a4.x), av1 = pk2(a4.y, a4.y);
        ull av2 = pk2(a4.z, a4.z), av3 = pk2(a4.w, a4.w);
        uint4 xq = xh[dwl + s * 8 + (lane >> 2)];
        U8 xu; xu.u = xq;
#pragma unroll
        for (int jp = 0; jp < 4; jp++) {
            float2 xf = __half22float2(xu.h2[jp]);
            ull xp = pk2(xf.x, xf.y);
            accp[jp][0] = ffma2(xp, av0, accp[jp][0]);
            accp[jp][1] = ffma2(xp, av1, accp[jp][1]);
            accp[jp][2] = ffma2(xp, av2, accp[jp][2]);
            accp[jp][3] = ffma2(xp, av3, accp[jp][3]);
        }
    }
#pragma unroll
    for (int mask = 4; mask <= 16; mask <<= 1)
#pragma unroll
        for (int jp = 0; jp < 4; jp++)
#pragma unroll
            for (int k = 0; k < 4; k++) {
                ull o = __shfl_xor_sync(0xffffffffu, accp[jp][k], mask);
                accp[jp][k] = fadd2(accp[jp][k], o);
            }
    if (lane < 4) {
#pragma unroll
        for (int jp = 0; jp < 4; jp++)
#pragma unroll
            for (int k = 0; k < 4; k++)
                red[(W * 4 + jp) * 16 + lane * 4 + k] = accp[jp][k];
    }
    __syncthreads();

    if (t < 64) {                       // t = jp*16 + r
        int jp = t >> 4, r = t & 15;
        ull s = red[jp * 16 + r];
#pragma unroll
        for (int q = 1; q < 8; q++) s = fadd2(s, red[(q * 4 + jp) * 16 + r]);
        g_hp[(chunk * 4 + part) * 64 + t] = s;
    }
}

// ---------------------------------------------------------------- k_h2: reduce+quantize
__global__ void k_h2() {
    int idx = blockIdx.x * blockDim.x + threadIdx.x;
    if (idx >= NCH * 64) return;
    int chunk = idx >> 6, t64 = idx & 63;
    ull s = g_hp[(chunk * 4 + 0) * 64 + t64];
#pragma unroll
    for (int p = 1; p < 4; p++)
        s = fadd2(s, g_hp[(chunk * 4 + p) * 64 + t64]);
    float lo, hi; up2(s, lo, hi);
    lo = __half2float(__float2half(2.0f * lo));   // fold x2, quantize (as reference)
    hi = __half2float(__float2half(2.0f * hi));
    int jp = t64 >> 4, r = t64 & 15;
    g_h[chunk * 64 + r * 4 + jp] = pk2(lo, hi);
}

// ---------------------------------------------------------------- k_y: y = (2h).B
__global__ void __launch_bounds__(TPB) k_y(
    const float* __restrict__ lB,
    const int*   __restrict__ wids,
    float*       __restrict__ out)
{
    int chunk = blockIdx.x >> 2;
    int part  = blockIdx.x & 3;
    int w     = chunk / SLOTS;
    int slot  = chunk % SLOTS;

    __shared__ ScanSm S;
    __shared__ ull hsf[64];
    __shared__ int shrow[8];

    int t = threadIdx.x, lane = t & 31, W = t >> 5;
    int mt[IPT], excl;
    int m = scan_rows(wids, w, &S, t, lane, W, &excl, mt);
    if (slot * CH >= m) return;
    int base = t * IPT;
#pragma unroll
    for (int k = 0; k < IPT; k++)
        if (mt[k]) S.slist[excl++] = base + k;
    __syncthreads();

    int nr = min(CH, m - slot * CH);
    if (t < CH) {
        int rr = (t < nr) ? S.slist[slot * CH + t] : -1;
        shrow[t] = rr;
    }
    if (t < 64) hsf[t] = g_h[chunk * 64 + t];
    __syncthreads();

    const float* B = lB + (size_t)w * R * D;
    int c4 = part * 256 + t;            // this thread's float4 column

    ull accp[4][4];
#pragma unroll
    for (int jp = 0; jp < 4; jp++)
#pragma unroll
        for (int k = 0; k < 4; k++) accp[jp][k] = 0ull;

#pragma unroll
    for (int r = 0; r < 16; r++) {      // 16 independent LDG.128 -> MLP 16
        float4 b4 = ((const float4*)B)[r * (D / 4) + c4];
        ull bv0 = pk2(b4.x, b4.x), bv1 = pk2(b4.y, b4.y);
        ull bv2 = pk2(b4.z, b4.z), bv3 = pk2(b4.w, b4.w);
#pragma unroll
        for (int jp = 0; jp < 4; jp++) {
            ull hv = hsf[r * 4 + jp];
            accp[jp][0] = ffma2(hv, bv0, accp[jp][0]);
            accp[jp][1] = ffma2(hv, bv1, accp[jp][1]);
            accp[jp][2] = ffma2(hv, bv2, accp[jp][2]);
            accp[jp][3] = ffma2(hv, bv3, accp[jp][3]);
        }
    }

#pragma unroll
    for (int jp = 0; jp < 4; jp++) {
        float l0, h0, l1, h1, l2, h2, l3, h3;
        up2(accp[jp][0], l0, h0); up2(accp[jp][1], l1, h1);
        up2(accp[jp][2], l2, h2); up2(accp[jp][3], l3, h3);
        int ra = shrow[2 * jp], rb = shrow[2 * jp + 1];
        if (ra >= 0) {
            __half2 q0 = __floats2half2_rn(l0, l1);
            __half2 q1 = __floats2half2_rn(l2, l3);
            if (ra < 1024) {
                ((uint2*)((__half*)g_y4 + (size_t)ra * D))[c4] =
                    make_uint2(*(unsigned*)&q0, *(unsigned*)&q1);
            } else {                    // pass-through: straight to out (quantized)
                float2 f0 = __half22float2(q0), f1 = __half22float2(q1);
                ((float4*)out)[(size_t)(ra - 768) * (D / 4) + c4] =
                    make_float4(f0.x, f0.y, f1.x, f1.y);
            }
        }
        if (rb >= 0) {
            __half2 q0 = __floats2half2_rn(h0, h1);
            __half2 q1 = __floats2half2_rn(h2, h3);
            if (rb < 1024) {
                ((uint2*)((__half*)g_y4 + (size_t)rb * D))[c4] =
                    make_uint2(*(unsigned*)&q0, *(unsigned*)&q1);
            } else {
                float2 f0 = __half22float2(q0), f1 = __half22float2(q1);
                ((float4*)out)[(size_t)(rb - 768) * (D / 4) + c4] =
                    make_float4(f0.x, f0.y, f1.x, f1.y);
            }
        }
    }
}

// ---------------------------------------------------------------- finalize (o<256 only)
__global__ void k_final(float* __restrict__ out) {
    const int UPR = D / 8;
    int idx = blockIdx.x * blockDim.x + threadIdx.x;
    if (idx >= 256 * UPR) return;
    int o  = idx / UPR;
    int dv = idx % UPR;

    U8 a, b, c, d, rr;
    a.u = g_y4[(size_t)(4 * o + 0) * UPR + dv];
    b.u = g_y4[(size_t)(4 * o + 1) * UPR + dv];
    c.u = g_y4[(size_t)(4 * o + 2) * UPR + dv];
    d.u = g_y4[(size_t)(4 * o + 3) * UPR + dv];
#pragma unroll
    for (int k = 0; k < 4; k++)         // sequential fp16 adds, ascending index
        rr.h2[k] = __hadd2(__hadd2(__hadd2(a.h2[k], b.h2[k]), c.h2[k]), d.h2[k]);

    float4 f0, f1;
    f0.x = __half2float(rr.h[0]); f0.y = __half2float(rr.h[1]);
    f0.z = __half2float(rr.h[2]); f0.w = __half2float(rr.h[3]);
    f1.x = __half2float(rr.h[4]); f1.y = __half2float(rr.h[5]);
    f1.z = __half2float(rr.h[6]); f1.w = __half2float(rr.h[7]);
    ((float4*)out)[idx * 2]     = f0;
    ((float4*)out)[idx * 2 + 1] = f1;
}

// ---------------------------------------------------------------- launch
extern "C" void kernel_launch(void* const* d_in, const int* in_sizes, int n_in,
                              void* d_out, int out_size) {
    const float* x    = (const float*)d_in[0];
    const float* lA   = (const float*)d_in[1];
    const float* lB   = (const float*)d_in[2];
    const int*   xids = (const int*)d_in[3];
    const int*   wids = (const int*)d_in[4];
    float*       out  = (float*)d_out;

    k_h1<<<NCH * PARTS, TPB>>>(x, lA, xids, wids);
    k_h2<<<(NCH * 64 + TPB - 1) / TPB, TPB>>>();
    k_y<<<NCH * PARTS, TPB>>>(lB, wids, out);
    k_final<<<(256 * (D / 8) + TPB - 1) / TPB, TPB>>>(out);
}

// round 11
// speedup vs baseline: 1.0078x; 1.0078x over previous
#include <cuda_runtime.h>
#include <cuda_fp16.h>

#define D      4096
#define R      16
#define NS     192
#define LB     1280
#define TPB    256
#define CH     4
#define SLOTS  10                     // chunk slots per adapter (m <= 40)
#define IPT    (LB / TPB)             // 5

typedef unsigned long long ull;
union U8 { uint4 u; __half2 h2[4]; __half h[8]; };

// ---- device scratch ----
__device__ uint4 g_y4[(size_t)1024 * (D / 8)];  // fp16 y, summed-segment rows only

// ---- packed f32x2 helpers (sm_100+) ----
__device__ __forceinline__ ull pk2(float lo, float hi) {
    ull r; asm("mov.b64 %0, {%1, %2};" : "=l"(r) : "f"(lo), "f"(hi)); return r;
}
__device__ __forceinline__ void up2(ull v, float& lo, float& hi) {
    asm("mov.b64 {%0, %1}, %2;" : "=f"(lo), "=f"(hi) : "l"(v));
}
__device__ __forceinline__ ull ffma2(ull a, ull b, ull c) {
    ull d; asm("fma.rn.f32x2 %0, %1, %2, %3;" : "=l"(d) : "l"(a), "l"(b), "l"(c)); return d;
}
__device__ __forceinline__ ull fadd2(ull a, ull b) {
    ull d; asm("add.rn.f32x2 %0, %1, %2;" : "=l"(d) : "l"(a), "l"(b)); return d;
}

// ---------------------------------------------------------------- compute
__global__ void __launch_bounds__(TPB, 4) k_compute(
    const float* __restrict__ x,
    const float* __restrict__ lA,
    const float* __restrict__ lB,
    const int*   __restrict__ xids,
    const int*   __restrict__ wids,
    float*       __restrict__ out)
{
    int w    = blockIdx.x / SLOTS;
    int slot = blockIdx.x % SLOTS;

    __shared__ uint2 xh[4096];          // 32 KB: d-major, 2 half2 row-pairs
    __shared__ ull   red[16 * 16];      // 2 KB: [warp*2+jp][r]
    __shared__ ull   hsf[32];           // [r*2+jp] packed quantized (2h)
    __shared__ int   swarp[8];
    __shared__ int   stot;
    __shared__ int   slist[64];
    __shared__ int   shrow[4];
    __shared__ int   shxid[4];

    int t = threadIdx.x, lane = t & 31, W = t >> 5;

    // ---- in-block gather scan for adapter w ----
    int base = t * IPT;
    int mt[IPT];
    int cnt = 0;
#pragma unroll
    for (int k = 0; k < IPT; k++) {
        mt[k] = (wids[base + k] == w) ? 1 : 0;
        cnt += mt[k];
    }
    int incl = cnt;
#pragma unroll
    for (int o = 1; o < 32; o <<= 1) {
        int v = __shfl_up_sync(0xffffffffu, incl, o);
        if (lane >= o) incl += v;
    }
    if (lane == 31) swarp[W] = incl;
    __syncthreads();
    if (t == 0) {
        int s = 0;
#pragma unroll
        for (int q = 0; q < 8; q++) { int v = swarp[q]; swarp[q] = s; s += v; }
        stot = s;
    }
    __syncthreads();
    int m = stot;
    if (slot * CH >= m) return;         // dead slot
    int excl = incl - cnt + swarp[W];
#pragma unroll
    for (int k = 0; k < IPT; k++)
        if (mt[k]) slist[excl++] = base + k;
    __syncthreads();

    int nr = min(CH, m - slot * CH);
    if (t < CH) {
        int rr = (t < nr) ? slist[slot * CH + t] : -1;
        shrow[t] = rr;
        shxid[t] = (rr >= 0) ? xids[rr] : -1;
    }
    __syncthreads();

    // ---- stage x (lossless fp16), d-major, 2 row-pairs per d ----
    {
        int xid[4];
#pragma unroll
        for (int j = 0; j < 4; j++) xid[j] = shxid[j];
#pragma unroll
        for (int i = 0; i < 16; i++) {
            int d = t + i * TPB;
            float v[4];
#pragma unroll
            for (int j = 0; j < 4; j++)
                v[j] = (xid[j] >= 0) ? x[(size_t)xid[j] * D + d] : 0.0f;
            __half2 p0 = __floats2half2_rn(v[0], v[1]);
            __half2 p1 = __floats2half2_rn(v[2], v[3]);
            xh[d] = make_uint2(*(unsigned*)&p0, *(unsigned*)&p1);
        }
    }
    __syncthreads();

    // ---- phase 1: h = x . A over this warp's 512-d stripe ----
    const float* A = lA + (size_t)w * D * R;
    ull accp[2][4];
#pragma unroll
    for (int jp = 0; jp < 2; jp++)
#pragma unroll
        for (int k = 0; k < 4; k++) accp[jp][k] = 0ull;

    int dw = W * 512;
#pragma unroll 4
    for (int s = 0; s < 64; s++) {
        float4 a4 = ((const float4*)A)[(dw + s * 8) * 4 + lane];   // 512B/warp
        ull av0 = pk2(a4.x, a4.x), av1 = pk2(a4.y, a4.y);
        ull av2 = pk2(a4.z, a4.z), av3 = pk2(a4.w, a4.w);
        uint2 xq = xh[dw + s * 8 + (lane >> 2)];                   // LDS.64 bcast
#pragma unroll
        for (int jp = 0; jp < 2; jp++) {
            float2 xf = __half22float2(*(__half2*)(jp ? &xq.y : &xq.x));
            ull xp = pk2(xf.x, xf.y);
            accp[jp][0] = ffma2(xp, av0, accp[jp][0]);
            accp[jp][1] = ffma2(xp, av1, accp[jp][1]);
            accp[jp][2] = ffma2(xp, av2, accp[jp][2]);
            accp[jp][3] = ffma2(xp, av3, accp[jp][3]);
        }
    }

    // reduce across lanes sharing the same r-quad (lane bits 2..4)
#pragma unroll
    for (int mask = 4; mask <= 16; mask <<= 1)
#pragma unroll
        for (int jp = 0; jp < 2; jp++)
#pragma unroll
            for (int k = 0; k < 4; k++) {
                ull o = __shfl_xor_sync(0xffffffffu, accp[jp][k], mask);
                accp[jp][k] = fadd2(accp[jp][k], o);
            }
    if (lane < 4) {
#pragma unroll
        for (int jp = 0; jp < 2; jp++)
#pragma unroll
            for (int k = 0; k < 4; k++)
                red[(W * 2 + jp) * 16 + lane * 4 + k] = accp[jp][k];
    }
    __syncthreads();

    // cross-warp reduce + fp16-quantize h with x2 folded in (exact scale)
    if (t < 32) {
        int jp = t >> 4, r = t & 15;
        ull s = red[jp * 16 + r];
#pragma unroll
        for (int q = 1; q < 8; q++) s = fadd2(s, red[(q * 2 + jp) * 16 + r]);
        float lo, hi; up2(s, lo, hi);
        lo = __half2float(__float2half(2.0f * lo));
        hi = __half2float(__float2half(2.0f * hi));
        hsf[r * 2 + jp] = pk2(lo, hi);
    }
    __syncthreads();

    // ---- phase 2: y = (2h) . B (coalesced; pass-through rows go to out) ----
    const float* B = lB + (size_t)w * R * D;
#pragma unroll
    for (int c = 0; c < 4; c++) {
        int c4 = t + c * TPB;
#pragma unroll
        for (int jp = 0; jp < 2; jp++)
#pragma unroll
            for (int k = 0; k < 4; k++) accp[jp][k] = 0ull;
#pragma unroll 4
        for (int r = 0; r < 16; r++) {
            float4 b4 = ((const float4*)B)[r * (D / 4) + c4];
            ull bv0 = pk2(b4.x, b4.x), bv1 = pk2(b4.y, b4.y);
            ull bv2 = pk2(b4.z, b4.z), bv3 = pk2(b4.w, b4.w);
#pragma unroll
            for (int jp = 0; jp < 2; jp++) {
                ull hv = hsf[r * 2 + jp];
                accp[jp][0] = ffma2(hv, bv0, accp[jp][0]);
                accp[jp][1] = ffma2(hv, bv1, accp[jp][1]);
                accp[jp][2] = ffma2(hv, bv2, accp[jp][2]);
                accp[jp][3] = ffma2(hv, bv3, accp[jp][3]);
            }
        }
#pragma unroll
        for (int jp = 0; jp < 2; jp++) {
            float l0, h0, l1, h1, l2, h2, l3, h3;
            up2(accp[jp][0], l0, h0); up2(accp[jp][1], l1, h1);
            up2(accp[jp][2], l2, h2); up2(accp[jp][3], l3, h3);
            int ra = shrow[2 * jp], rb = shrow[2 * jp + 1];
            if (ra >= 0) {
                __half2 q0 = __floats2half2_rn(l0, l1);
                __half2 q1 = __floats2half2_rn(l2, l3);
                if (ra < 1024) {
                    ((uint2*)((__half*)g_y4 + (size_t)ra * D))[c4] =
                        make_uint2(*(unsigned*)&q0, *(unsigned*)&q1);
                } else {            // pass-through: fp16-quantized, widened to f32
                    float2 f0 = __half22float2(q0), f1 = __half22float2(q1);
                    ((float4*)out)[(size_t)(ra - 768) * (D / 4) + c4] =
                        make_float4(f0.x, f0.y, f1.x, f1.y);
                }
            }
            if (rb >= 0) {
                __half2 q0 = __floats2half2_rn(h0, h1);
                __half2 q1 = __floats2half2_rn(h2, h3);
                if (rb < 1024) {
                    ((uint2*)((__half*)g_y4 + (size_t)rb * D))[c4] =
                        make_uint2(*(unsigned*)&q0, *(unsigned*)&q1);
                } else {
                    float2 f0 = __half22float2(q0), f1 = __half22float2(q1);
                    ((float4*)out)[(size_t)(rb - 768) * (D / 4) + c4] =
                        make_float4(f0.x, f0.y, f1.x, f1.y);
                }
            }
        }
    }
}

// ---------------------------------------------------------------- finalize (o<256)
// thread handles 4 consecutive dv -> 16 independent LDG.128 up-front (MLP 16)
__global__ void __launch_bounds__(TPB) k_final(float* __restrict__ out) {
    const int UPR = D / 8;                       // 512 uint4 per row
    int idx = blockIdx.x * blockDim.x + threadIdx.x;   // 32768 threads
    int o   = idx >> 7;
    int dv0 = (idx & 127) * 4;

    uint4 v[4][4];
#pragma unroll
    for (int rj = 0; rj < 4; rj++)
#pragma unroll
        for (int p = 0; p < 4; p++)
            v[rj][p] = g_y4[(size_t)(4 * o + rj) * UPR + dv0 + p];

#pragma unroll
    for (int p = 0; p < 4; p++) {
        U8 a, b, c, d, rr;
        a.u = v[0][p]; b.u = v[1][p]; c.u = v[2][p]; d.u = v[3][p];
#pragma unroll
        for (int k = 0; k < 4; k++)     // sequential fp16 adds, ascending index
            rr.h2[k] = __hadd2(__hadd2(__hadd2(a.h2[k], b.h2[k]), c.h2[k]), d.h2[k]);
        float4 f0, f1;
        f0.x = __half2float(rr.h[0]); f0.y = __half2float(rr.h[1]);
        f0.z = __half2float(rr.h[2]); f0.w = __half2float(rr.h[3]);
        f1.x = __half2float(rr.h[4]); f1.y = __half2float(rr.h[5]);
        f1.z = __half2float(rr.h[6]); f1.w = __half2float(rr.h[7]);
        int u = o * UPR + dv0 + p;
        ((float4*)out)[u * 2]     = f0;
        ((float4*)out)[u * 2 + 1] = f1;
    }
}

// ---------------------------------------------------------------- launch
extern "C" void kernel_launch(void* const* d_in, const int* in_sizes, int n_in,
                              void* d_out, int out_size) {
    const float* x    = (const float*)d_in[0];
    const float* lA   = (const float*)d_in[1];
    const float* lB   = (const float*)d_in[2];
    const int*   xids = (const int*)d_in[3];
    const int*   wids = (const int*)d_in[4];
    float*       out  = (float*)d_out;

    k_compute<<<NS * SLOTS, TPB>>>(x, lA, lB, xids, wids, out);
    k_final<<<128, TPB>>>(out);
}